// round 15
// baseline (speedup 1.0000x reference)
#include <cuda_runtime.h>
#include <cuda_bf16.h>
#include <cstdint>
#include <math.h>

// Problem constants
#define NT    16384      // B*T tokens
#define DIMQ  512
#define HEADS 8
#define DHEAD 64
#define TLEN  4096       // T per batch
#define NB    4          // batch
#define NSPLIT 32        // T-splits for ctx partials (128 tokens each)

// ---------------------------------------------------------------------------
// Scratch (device globals — no allocation allowed)
// ---------------------------------------------------------------------------
__device__ __nv_bfloat16  g_qh[NT * DIMQ];
__device__ __nv_bfloat16  g_ql[NT * DIMQ];
__device__ __nv_bfloat16  g_kh[NT * DIMQ];
__device__ __nv_bfloat16  g_kl[NT * DIMQ];
__device__ __nv_bfloat16  g_vh[NT * DIMQ];
__device__ __nv_bfloat16  g_vl[NT * DIMQ];
__device__ __nv_bfloat16  g_xh[NT * DIMQ];
__device__ __nv_bfloat16  g_xl[NT * DIMQ];
__device__ __nv_bfloat16  g_atth[NT * DIMQ];
__device__ __nv_bfloat16  g_attl[NT * DIMQ];
__device__ __nv_bfloat16  g_wh[4 * DIMQ * DIMQ];
__device__ __nv_bfloat16  g_wl[4 * DIMQ * DIMQ];
__device__ float          g_ctxp[NB * HEADS * NSPLIT * DHEAD * DHEAD];
__device__ float          g_ksump[NB * HEADS * NSPLIT * DHEAD];
__device__ __nv_bfloat16  g_cth[NB * HEADS * DHEAD * DHEAD];  // ctx^T hi
__device__ __nv_bfloat16  g_ctl[NB * HEADS * DHEAD * DHEAD];  // ctx^T lo
__device__ float          g_ksum[NB * HEADS * DHEAD];

#define SWZ128(x) ((x) ^ (((x) >> 3) & 0x70))

// ---------------------------------------------------------------------------
// warp-MMA helpers
// ---------------------------------------------------------------------------
__device__ __forceinline__ uint32_t smem_u32(const void* p) {
    uint32_t a;
    asm("{ .reg .u64 t; cvta.to.shared.u64 t, %1; cvt.u32.u64 %0, t; }"
        : "=r"(a) : "l"(p));
    return a;
}

__device__ __forceinline__ void cp_async16(uint32_t saddr, const void* gaddr) {
    asm volatile("cp.async.cg.shared.global [%0], [%1], 16;"
                 :: "r"(saddr), "l"(gaddr) : "memory");
}
#define CP_COMMIT() asm volatile("cp.async.commit_group;" ::: "memory")
#define CP_WAIT1()  asm volatile("cp.async.wait_group 1;" ::: "memory")
#define CP_WAIT0()  asm volatile("cp.async.wait_group 0;" ::: "memory")

__device__ __forceinline__ void ldsm4(uint32_t* r, uint32_t addr) {
    asm volatile("ldmatrix.sync.aligned.m8n8.x4.shared.b16 {%0,%1,%2,%3}, [%4];"
                 : "=r"(r[0]), "=r"(r[1]), "=r"(r[2]), "=r"(r[3]) : "r"(addr));
}
__device__ __forceinline__ void ldsm4t(uint32_t* r, uint32_t addr) {
    asm volatile("ldmatrix.sync.aligned.m8n8.x4.trans.shared.b16 {%0,%1,%2,%3}, [%4];"
                 : "=r"(r[0]), "=r"(r[1]), "=r"(r[2]), "=r"(r[3]) : "r"(addr));
}

__device__ __forceinline__ void mma_bf16(float* c, const uint32_t* a,
                                         const uint32_t* b) {
    asm volatile(
        "mma.sync.aligned.m16n8k16.row.col.f32.bf16.bf16.f32 "
        "{%0,%1,%2,%3}, {%4,%5,%6,%7}, {%8,%9}, {%0,%1,%2,%3};"
        : "+f"(c[0]), "+f"(c[1]), "+f"(c[2]), "+f"(c[3])
        : "r"(a[0]), "r"(a[1]), "r"(a[2]), "r"(a[3]), "r"(b[0]), "r"(b[1]));
}

__device__ __forceinline__ float lds_bf16(uint32_t a) {
    uint32_t v;
    asm volatile("ld.shared.u16 %0, [%1];" : "=r"(v) : "r"(a));
    __nv_bfloat16_raw r; r.x = (unsigned short)v;
    return __bfloat162float(__nv_bfloat16(r));
}

__device__ __forceinline__ float2 bf2_to_f2(uint32_t u) {
    __nv_bfloat162 p = *reinterpret_cast<__nv_bfloat162*>(&u);
    return __bfloat1622float2(p);
}

// ---------------------------------------------------------------------------
// fp32 -> bf16 hi/lo split conversion
// ---------------------------------------------------------------------------
__global__ __launch_bounds__(256) void hilo_kernel(
    const float* __restrict__ in, __nv_bfloat16* __restrict__ hi,
    __nv_bfloat16* __restrict__ lo)
{
    size_t i = ((size_t)blockIdx.x * 256 + threadIdx.x) * 4;
    float4 v = *(const float4*)(in + i);
    __nv_bfloat16 h0 = __float2bfloat16(v.x);
    __nv_bfloat16 h1 = __float2bfloat16(v.y);
    __nv_bfloat16 h2 = __float2bfloat16(v.z);
    __nv_bfloat16 h3 = __float2bfloat16(v.w);
    __nv_bfloat16 l0 = __float2bfloat16(v.x - __bfloat162float(h0));
    __nv_bfloat16 l1 = __float2bfloat16(v.y - __bfloat162float(h1));
    __nv_bfloat16 l2 = __float2bfloat16(v.z - __bfloat162float(h2));
    __nv_bfloat16 l3 = __float2bfloat16(v.w - __bfloat162float(h3));
    *(__nv_bfloat162*)(hi + i)     = __nv_bfloat162(h0, h1);
    *(__nv_bfloat162*)(hi + i + 2) = __nv_bfloat162(h2, h3);
    *(__nv_bfloat162*)(lo + i)     = __nv_bfloat162(l0, l1);
    *(__nv_bfloat162*)(lo + i + 2) = __nv_bfloat162(l2, l3);
}

struct WPtrs { const float* w[4]; };
__global__ __launch_bounds__(256) void hilo_w4_kernel(
    WPtrs p, __nv_bfloat16* __restrict__ hi, __nv_bfloat16* __restrict__ lo)
{
    const int WN = DIMQ * DIMQ;
    const float* in = p.w[blockIdx.y];
    size_t off = (size_t)blockIdx.y * WN;
    size_t i = ((size_t)blockIdx.x * 256 + threadIdx.x) * 4;
    float4 v = *(const float4*)(in + i);
    __nv_bfloat16 h0 = __float2bfloat16(v.x);
    __nv_bfloat16 h1 = __float2bfloat16(v.y);
    __nv_bfloat16 h2 = __float2bfloat16(v.z);
    __nv_bfloat16 h3 = __float2bfloat16(v.w);
    __nv_bfloat16 l0 = __float2bfloat16(v.x - __bfloat162float(h0));
    __nv_bfloat16 l1 = __float2bfloat16(v.y - __bfloat162float(h1));
    __nv_bfloat16 l2 = __float2bfloat16(v.z - __bfloat162float(h2));
    __nv_bfloat16 l3 = __float2bfloat16(v.w - __bfloat162float(h3));
    *(__nv_bfloat162*)(hi + off + i)     = __nv_bfloat162(h0, h1);
    *(__nv_bfloat162*)(hi + off + i + 2) = __nv_bfloat162(h2, h3);
    *(__nv_bfloat162*)(lo + off + i)     = __nv_bfloat162(l0, l1);
    *(__nv_bfloat162*)(lo + off + i + 2) = __nv_bfloat162(l2, l3);
}

// ---------------------------------------------------------------------------
// bf16x3 GEMM, BM=128 x BN=256, 512 threads (warp grid 4m x 4n, tile 32x64).
// 2-stage cp.async pipeline, 96KB/stage. Fused per-head softmax epilogue.
// Cf != nullptr -> fp32 output; else bf16 hi/lo via op.h/l[widx].
// ---------------------------------------------------------------------------
#define GBM 128
#define GBN 256
#define GKS 64
#define GNSL (DIMQ / GKS)                 // 8
#define A_TILE 16384                      // 128 x 128B
#define W_TILE 32768                      // 256 x 128B
#define STAGE_BYTES (2 * A_TILE + 2 * W_TILE)   // 98304
#define GEMM_SMEM (2 * STAGE_BYTES)       // 196608

struct OutPtrs { __nv_bfloat16 *h[3]; __nv_bfloat16 *l[3]; };

__global__ __launch_bounds__(512) void gemm_bf16x3_kernel(
    const __nv_bfloat16* __restrict__ Ah, const __nv_bfloat16* __restrict__ Al,
    const __nv_bfloat16* __restrict__ Wh, const __nv_bfloat16* __restrict__ Wl,
    const float* __restrict__ b0, const float* __restrict__ b1,
    const float* __restrict__ b2,
    float* __restrict__ Cf, OutPtrs op, int sm_mask)
{
    extern __shared__ __align__(1024) char sm[];
    uint32_t smb = smem_u32(sm);

    const int tid  = threadIdx.x;
    const int wid  = tid >> 5;
    const int lane = tid & 31;
    const int m0 = blockIdx.y * GBM;
    const int n0 = blockIdx.x * GBN;

    const int warp_m = wid & 3;        // 4 m-warps x 32 rows
    const int warp_n = wid >> 2;       // 4 n-warps x 64 cols (= one head)
    const int mbase = warp_m * 32;
    const int nbase = warp_n * 64;

    const int widx = (n0 + nbase) >> 9;        // which of up to 3 weight mats
    const int colg = (n0 + nbase) & 511;       // col within that matrix
    const float* bias = (widx == 0) ? b0 : (widx == 1) ? b1 : b2;
    const bool do_sm  = (sm_mask >> widx) & 1;

    const int lr = lane & 7;
    const int g  = lane >> 3;
    const uint32_t aoff = (uint32_t)(((g & 1) * 8 + lr) * 128 + (g >> 1) * 16);
    const uint32_t boff = (uint32_t)(((g >> 1) * 8 + lr) * 128 + (g & 1) * 16);

    float acc[2][8][4];
#pragma unroll
    for (int i = 0; i < 2; i++)
#pragma unroll
        for (int j = 0; j < 8; j++)
#pragma unroll
            for (int c = 0; c < 4; c++) acc[i][j][c] = 0.0f;

    auto load_stage = [&](int s) {
        uint32_t stb = smb + (uint32_t)(s & 1) * STAGE_BYTES;
        int k0 = s * GKS;
        // A hi/lo: 2048 chunks (j 0-1 hi, 2-3 lo)
#pragma unroll
        for (int j = 0; j < 4; j++) {
            int idx = tid + j * 512;
            const __nv_bfloat16* src = (j < 2) ? Ah : Al;
            uint32_t tb = stb + ((j < 2) ? 0u : (uint32_t)A_TILE);
            int rem = idx & 1023;
            int row = rem >> 3, ch = rem & 7;
            uint32_t sa = tb + SWZ128((uint32_t)(row * 128 + ch * 16));
            cp_async16(sa, src + (size_t)(m0 + row) * DIMQ + k0 + ch * 8);
        }
        // W hi/lo: 4096 chunks (j 0-3 hi, 4-7 lo)
#pragma unroll
        for (int j = 0; j < 8; j++) {
            int idx = tid + j * 512;
            const __nv_bfloat16* src = (j < 4) ? Wh : Wl;
            uint32_t tb = stb + 2 * A_TILE + ((j < 4) ? 0u : (uint32_t)W_TILE);
            int rem = idx & 2047;
            int row = rem >> 3, ch = rem & 7;
            uint32_t sa = tb + SWZ128((uint32_t)(row * 128 + ch * 16));
            cp_async16(sa, src + (size_t)(n0 + row) * DIMQ + k0 + ch * 8);
        }
    };

    load_stage(0); CP_COMMIT();

    for (int s = 0; s < GNSL; s++) {
        if (s + 1 < GNSL) { load_stage(s + 1); CP_COMMIT(); CP_WAIT1(); }
        else              { CP_WAIT0(); }
        __syncthreads();

        uint32_t stb  = smb + (uint32_t)(s & 1) * STAGE_BYTES;
        uint32_t ah_b = stb;
        uint32_t wh_b = stb + 2 * A_TILE;

#pragma unroll
        for (int ks = 0; ks < 4; ks++) {
            uint32_t ksb = (uint32_t)(ks * 32);
            uint32_t aH[2][4], aL[2][4], bH[4][4], bL[4][4];
#pragma unroll
            for (int am = 0; am < 2; am++) {
                uint32_t ad = ah_b + (uint32_t)((mbase + am * 16) * 128)
                            + SWZ128(aoff + ksb);
                ldsm4(aH[am], ad);
                ldsm4(aL[am], ad + A_TILE);
            }
#pragma unroll
            for (int nq = 0; nq < 4; nq++) {
                uint32_t bd = wh_b + (uint32_t)((nbase + nq * 16) * 128)
                            + SWZ128(boff + ksb);
                ldsm4(bH[nq], bd);
                ldsm4(bL[nq], bd + W_TILE);
            }
#pragma unroll
            for (int am = 0; am < 2; am++)
#pragma unroll
                for (int na = 0; na < 8; na++) {
                    const uint32_t* bh = &bH[na >> 1][(na & 1) * 2];
                    const uint32_t* bl = &bL[na >> 1][(na & 1) * 2];
                    mma_bf16(acc[am][na], aH[am], bh);
                    mma_bf16(acc[am][na], aH[am], bl);
                    mma_bf16(acc[am][na], aL[am], bh);
                }
        }
        __syncthreads();
    }

    const int row_in = lane >> 2;
    const int col_in = (lane & 3) * 2;

    __nv_bfloat16* Oh = op.h[widx];
    __nv_bfloat16* Ol = op.l[widx];

    float bb[16];
#pragma unroll
    for (int na = 0; na < 8; na++) {
        float2 b = *(const float2*)&bias[colg + na * 8 + col_in];
        bb[na * 2] = b.x; bb[na * 2 + 1] = b.y;
    }

#pragma unroll
    for (int am = 0; am < 2; am++) {
#pragma unroll
        for (int sub = 0; sub < 2; sub++) {
            float v[16];
#pragma unroll
            for (int na = 0; na < 8; na++) {
                v[na * 2]     = acc[am][na][sub * 2]     + bb[na * 2];
                v[na * 2 + 1] = acc[am][na][sub * 2 + 1] + bb[na * 2 + 1];
            }
            if (do_sm) {
                float m = v[0];
#pragma unroll
                for (int i = 1; i < 16; i++) m = fmaxf(m, v[i]);
                m = fmaxf(m, __shfl_xor_sync(0xffffffffu, m, 1));
                m = fmaxf(m, __shfl_xor_sync(0xffffffffu, m, 2));
                float ssum = 0.0f;
#pragma unroll
                for (int i = 0; i < 16; i++) { v[i] = __expf(v[i] - m); ssum += v[i]; }
                ssum += __shfl_xor_sync(0xffffffffu, ssum, 1);
                ssum += __shfl_xor_sync(0xffffffffu, ssum, 2);
                float inv = 1.0f / ssum;
#pragma unroll
                for (int i = 0; i < 16; i++) v[i] *= inv;
            }
            int r = m0 + mbase + am * 16 + sub * 8 + row_in;
            if (Cf) {
#pragma unroll
                for (int na = 0; na < 8; na++) {
                    int c = colg + na * 8 + col_in;
                    *(float2*)&Cf[(size_t)r * DIMQ + c] =
                        make_float2(v[na * 2], v[na * 2 + 1]);
                }
            } else {
#pragma unroll
                for (int na = 0; na < 8; na++) {
                    int c = colg + na * 8 + col_in;
                    __nv_bfloat16 h0 = __float2bfloat16(v[na * 2]);
                    __nv_bfloat16 h1 = __float2bfloat16(v[na * 2 + 1]);
                    __nv_bfloat16 l0 = __float2bfloat16(v[na * 2]     - __bfloat162float(h0));
                    __nv_bfloat16 l1 = __float2bfloat16(v[na * 2 + 1] - __bfloat162float(h1));
                    *(__nv_bfloat162*)&Oh[(size_t)r * DIMQ + c] = __nv_bfloat162(h0, h1);
                    *(__nv_bfloat162*)&Ol[(size_t)r * DIMQ + c] = __nv_bfloat162(l0, l1);
                }
            }
        }
    }
}

// ---------------------------------------------------------------------------
// ctx partials via tensor cores. grid (32, NSPLIT=32), 128 threads.
// 32-token chunks (16KB stage) for higher occupancy.
// ---------------------------------------------------------------------------
#define CCH 32
#define CTILE (CCH * 128)                 // 4096
#define CSTAGE (4 * CTILE)                // 16384
#define CTX_SMEM (2 * CSTAGE)             // 32768

__global__ __launch_bounds__(128) void ctx_mma_kernel(
    const __nv_bfloat16* __restrict__ Kh, const __nv_bfloat16* __restrict__ Kl,
    const __nv_bfloat16* __restrict__ Vh, const __nv_bfloat16* __restrict__ Vl,
    float* __restrict__ ctxp, float* __restrict__ ksump)
{
    extern __shared__ __align__(1024) char sm[];
    uint32_t smb = smem_u32(sm);

    const int bh = blockIdx.x;
    const int s  = blockIdx.y;
    const int b = bh >> 3, h = bh & 7;
    const int tid = threadIdx.x;
    const int wid = tid >> 5, lane = tid & 31;

    const size_t tok0 = (size_t)b * TLEN + s * (TLEN / NSPLIT);
    const __nv_bfloat16* srcs[4] = {Kh, Kl, Vh, Vl};

    const int arow = (lane & 7) + 8 * ((lane >> 4) & 1);
    const int acolX = wid * 32 + 16 * ((lane >> 3) & 1);
    const int brow = (lane & 7) + 8 * ((lane >> 3) & 1);
    const int bcolX = 16 * ((lane >> 4) & 1);

    auto load_chunk = [&](int c, int buf) {
        uint32_t stb = smb + (uint32_t)buf * CSTAGE;
#pragma unroll
        for (int i = 0; i < (4 * CCH * 8) / 128; i++) {   // 8
            int idx  = tid + i * 128;
            int tile = idx / (CCH * 8);
            int rem  = idx % (CCH * 8);
            int row  = rem >> 3;
            int ch   = rem & 7;
            uint32_t sa = stb + (uint32_t)tile * CTILE
                        + SWZ128((uint32_t)(row * 128 + ch * 16));
            const void* ga = srcs[tile]
                + (tok0 + c * CCH + row) * DIMQ + h * DHEAD + ch * 8;
            cp_async16(sa, ga);
        }
    };

    float acc[8][4];
#pragma unroll
    for (int j = 0; j < 8; j++)
#pragma unroll
        for (int c = 0; c < 4; c++) acc[j][c] = 0.0f;
    float ksacc = 0.0f;

    load_chunk(0, 0); CP_COMMIT();

    const int NCH = (TLEN / NSPLIT) / CCH;  // 4
    for (int c = 0; c < NCH; c++) {
        if (c + 1 < NCH) { load_chunk(c + 1, (c + 1) & 1); CP_COMMIT(); CP_WAIT1(); }
        else             { CP_WAIT0(); }
        __syncthreads();

        uint32_t st = smb + (uint32_t)(c & 1) * CSTAGE;
#pragma unroll
        for (int kk = 0; kk < CCH / 16; kk++) {   // 2
            int t0 = kk * 16;
            uint32_t aH[4], aL[4], vH[4][4], vL[4][4];
            uint32_t ad = st + SWZ128((uint32_t)((t0 + arow) * 128 + acolX));
            ldsm4t(aH, ad);
            ldsm4t(aL, ad + CTILE);
#pragma unroll
            for (int nb2 = 0; nb2 < 4; nb2++) {
                uint32_t bd = st + 2 * CTILE
                    + SWZ128((uint32_t)((t0 + brow) * 128 + nb2 * 32 + bcolX));
                ldsm4t(vH[nb2], bd);
                ldsm4t(vL[nb2], bd + CTILE);
            }
#pragma unroll
            for (int nb = 0; nb < 8; nb++) {
                const uint32_t* bh_ = &vH[nb >> 1][(nb & 1) * 2];
                const uint32_t* bl_ = &vL[nb >> 1][(nb & 1) * 2];
                mma_bf16(acc[nb], aH, bh_);
                mma_bf16(acc[nb], aH, bl_);
                mma_bf16(acc[nb], aL, bh_);
            }
        }
        if (tid < 64) {
#pragma unroll 8
            for (int t = 0; t < CCH; t++) {
                uint32_t off = SWZ128((uint32_t)(t * 128 + tid * 2));
                ksacc += lds_bf16(st + off) + lds_bf16(st + CTILE + off);
            }
        }
        __syncthreads();
    }

    size_t obase = ((size_t)bh * NSPLIT + s) * (DHEAD * DHEAD);
    int r1 = wid * 16 + (lane >> 2);
    int ec = (lane & 3) * 2;
#pragma unroll
    for (int nb = 0; nb < 8; nb++) {
        int e = nb * 8 + ec;
        *(float2*)&ctxp[obase + (size_t)r1 * DHEAD + e] =
            make_float2(acc[nb][0], acc[nb][1]);
        *(float2*)&ctxp[obase + (size_t)(r1 + 8) * DHEAD + e] =
            make_float2(acc[nb][2], acc[nb][3]);
    }
    if (tid < 64)
        ksump[((size_t)bh * NSPLIT + s) * DHEAD + tid] = ksacc;
}

// ---------------------------------------------------------------------------
// Reduce ctx partials -> ctx^T bf16 hi/lo; reduce ksum partials -> fp32.
// ---------------------------------------------------------------------------
__global__ __launch_bounds__(256) void ctx_reduce_kernel(
    const float* __restrict__ ctxp, const float* __restrict__ ksump,
    __nv_bfloat16* __restrict__ cth, __nv_bfloat16* __restrict__ ctl,
    float* __restrict__ ksum)
{
    int bh = blockIdx.x;
    for (int idx = threadIdx.x; idx < DHEAD * DHEAD; idx += blockDim.x) {
        float s = 0.0f;
#pragma unroll
        for (int p = 0; p < NSPLIT; p++)
            s += ctxp[(size_t)(bh * NSPLIT + p) * DHEAD * DHEAD + idx];
        int d = idx >> 6, e = idx & 63;
        __nv_bfloat16 h = __float2bfloat16(s);
        size_t o = (size_t)bh * DHEAD * DHEAD + (size_t)e * DHEAD + d;
        cth[o] = h;
        ctl[o] = __float2bfloat16(s - __bfloat162float(h));
    }
    if (threadIdx.x < DHEAD) {
        float s = 0.0f;
#pragma unroll
        for (int p = 0; p < NSPLIT; p++)
            s += ksump[(size_t)(bh * NSPLIT + p) * DHEAD + threadIdx.x];
        ksum[bh * DHEAD + threadIdx.x] = s;
    }
}

// ---------------------------------------------------------------------------
// Apply attention via tensor cores.
// ---------------------------------------------------------------------------
#define AT_QH 0
#define AT_QL 16384
#define AT_CH 32768
#define AT_CL 40960
#define AT_KS 49152
#define AT_DI 49408
#define AT_SMEM 49920

__global__ __launch_bounds__(128) void attn_mma_kernel(
    const __nv_bfloat16* __restrict__ Qh, const __nv_bfloat16* __restrict__ Ql,
    const __nv_bfloat16* __restrict__ cth, const __nv_bfloat16* __restrict__ ctl,
    const float* __restrict__ ksum,
    __nv_bfloat16* __restrict__ outh, __nv_bfloat16* __restrict__ outl)
{
    extern __shared__ __align__(1024) char sm[];
    uint32_t smb = smem_u32(sm);
    float* ksum_s = (float*)(sm + AT_KS);
    float* dinv_s = (float*)(sm + AT_DI);

    const int bh = blockIdx.x;
    const int b = bh >> 3, h = bh & 7;
    const size_t tok0 = (size_t)b * TLEN + blockIdx.y * 128;
    const int tid = threadIdx.x;
    const int wid = tid >> 5, lane = tid & 31;

#pragma unroll
    for (int i = 0; i < 8; i++) {
        int idx = tid + i * 128;
        int row = idx >> 3, ch = idx & 7;
        uint32_t so = SWZ128((uint32_t)(row * 128 + ch * 16));
        const size_t go = (tok0 + row) * DIMQ + h * DHEAD + ch * 8;
        cp_async16(smb + AT_QH + so, Qh + go);
        cp_async16(smb + AT_QL + so, Ql + go);
    }
#pragma unroll
    for (int i = 0; i < 4; i++) {
        int idx = tid + i * 128;
        int row = idx >> 3, ch = idx & 7;
        uint32_t so = SWZ128((uint32_t)(row * 128 + ch * 16));
        const size_t go = (size_t)bh * DHEAD * DHEAD + (size_t)row * DHEAD + ch * 8;
        cp_async16(smb + AT_CH + so, cth + go);
        cp_async16(smb + AT_CL + so, ctl + go);
    }
    if (tid < 64) ksum_s[tid] = ksum[bh * DHEAD + tid];
    CP_COMMIT();
    CP_WAIT0();
    __syncthreads();

    {
        float dot = 0.0f;
#pragma unroll
        for (int ch = 0; ch < 8; ch++) {
            uint32_t so = SWZ128((uint32_t)(tid * 128 + ch * 16));
            uint4 wh4 = *(const uint4*)(sm + AT_QH + so);
            uint4 wl4 = *(const uint4*)(sm + AT_QL + so);
            const uint32_t wh[4] = {wh4.x, wh4.y, wh4.z, wh4.w};
            const uint32_t wl[4] = {wl4.x, wl4.y, wl4.z, wl4.w};
#pragma unroll
            for (int j = 0; j < 4; j++) {
                float2 fh = bf2_to_f2(wh[j]);
                float2 fl = bf2_to_f2(wl[j]);
                int d = ch * 8 + j * 2;
                dot += (fh.x + fl.x) * ksum_s[d];
                dot += (fh.y + fl.y) * ksum_s[d + 1];
            }
        }
        dinv_s[tid] = 1.0f / dot;
    }
    __syncthreads();

    const int lr = lane & 7;
    const int g  = lane >> 3;
    const uint32_t aoff = (uint32_t)(((g & 1) * 8 + lr) * 128 + (g >> 1) * 16);
    const uint32_t boff = (uint32_t)(((g >> 1) * 8 + lr) * 128 + (g & 1) * 16);
    const int mbase = wid * 32;

    float acc[2][8][4];
#pragma unroll
    for (int i = 0; i < 2; i++)
#pragma unroll
        for (int j = 0; j < 8; j++)
#pragma unroll
            for (int c = 0; c < 4; c++) acc[i][j][c] = 0.0f;

#pragma unroll
    for (int ks = 0; ks < 4; ks++) {
        uint32_t ksb = (uint32_t)(ks * 32);
        uint32_t aH[2][4], aL[2][4], bH[4][4], bL[4][4];
#pragma unroll
        for (int am = 0; am < 2; am++) {
            uint32_t ad = smb + AT_QH + (uint32_t)((mbase + am * 16) * 128)
                        + SWZ128(aoff + ksb);
            ldsm4(aH[am], ad);
            ldsm4(aL[am], ad + (AT_QL - AT_QH));
        }
#pragma unroll
        for (int nq = 0; nq < 4; nq++) {
            uint32_t bd = smb + AT_CH + (uint32_t)((nq * 16) * 128)
                        + SWZ128(boff + ksb);
            ldsm4(bH[nq], bd);
            ldsm4(bL[nq], bd + (AT_CL - AT_CH));
        }
#pragma unroll
        for (int am = 0; am < 2; am++)
#pragma unroll
            for (int na = 0; na < 8; na++) {
                const uint32_t* bh_ = &bH[na >> 1][(na & 1) * 2];
                const uint32_t* bl_ = &bL[na >> 1][(na & 1) * 2];
                mma_bf16(acc[am][na], aH[am], bh_);
                mma_bf16(acc[am][na], aH[am], bl_);
                mma_bf16(acc[am][na], aL[am], bh_);
            }
    }

    const int row_in = lane >> 2;
    const int col_in = (lane & 3) * 2;
#pragma unroll
    for (int am = 0; am < 2; am++) {
#pragma unroll
        for (int sub = 0; sub < 2; sub++) {
            int r = mbase + am * 16 + sub * 8 + row_in;
            float di = dinv_s[r];
#pragma unroll
            for (int na = 0; na < 8; na++) {
                int c = na * 8 + col_in;
                uint32_t so = SWZ128((uint32_t)(r * 128 + c * 2));
                float2 qh2 = bf2_to_f2(*(const uint32_t*)(sm + AT_QH + so));
                float2 ql2 = bf2_to_f2(*(const uint32_t*)(sm + AT_QL + so));
                float v0 = acc[am][na][sub * 2]     * di + qh2.x + ql2.x;
                float v1 = acc[am][na][sub * 2 + 1] * di + qh2.y + ql2.y;
                __nv_bfloat16 h0 = __float2bfloat16(v0);
                __nv_bfloat16 h1 = __float2bfloat16(v1);
                __nv_bfloat16 l0 = __float2bfloat16(v0 - __bfloat162float(h0));
                __nv_bfloat16 l1 = __float2bfloat16(v1 - __bfloat162float(h1));
                size_t idx = (tok0 + r) * DIMQ + h * DHEAD + c;
                *(__nv_bfloat162*)&outh[idx] = __nv_bfloat162(h0, h1);
                *(__nv_bfloat162*)&outl[idx] = __nv_bfloat162(l0, l1);
            }
        }
    }
}

// ---------------------------------------------------------------------------
extern "C" void kernel_launch(void* const* d_in, const int* in_sizes, int n_in,
                              void* d_out, int out_size)
{
    const float* x  = (const float*)d_in[0];
    const float* Wq = (const float*)d_in[1];
    const float* bq = (const float*)d_in[2];
    const float* Wk = (const float*)d_in[3];
    const float* bk = (const float*)d_in[4];
    const float* Wv = (const float*)d_in[5];
    const float* bv = (const float*)d_in[6];
    const float* Wp = (const float*)d_in[7];
    const float* bp = (const float*)d_in[8];
    float* out = (float*)d_out;

    float *ctxp, *ksump, *ksum;
    __nv_bfloat16 *qh, *ql, *kh, *kl, *vh, *vl, *xh, *xl, *atth, *attl, *wh, *wl, *cth, *ctl;
    cudaGetSymbolAddress((void**)&qh, g_qh);
    cudaGetSymbolAddress((void**)&ql, g_ql);
    cudaGetSymbolAddress((void**)&kh, g_kh);
    cudaGetSymbolAddress((void**)&kl, g_kl);
    cudaGetSymbolAddress((void**)&vh, g_vh);
    cudaGetSymbolAddress((void**)&vl, g_vl);
    cudaGetSymbolAddress((void**)&ctxp, g_ctxp);
    cudaGetSymbolAddress((void**)&ksump, g_ksump);
    cudaGetSymbolAddress((void**)&ksum, g_ksum);
    cudaGetSymbolAddress((void**)&cth, g_cth);
    cudaGetSymbolAddress((void**)&ctl, g_ctl);
    cudaGetSymbolAddress((void**)&xh, g_xh);
    cudaGetSymbolAddress((void**)&xl, g_xl);
    cudaGetSymbolAddress((void**)&atth, g_atth);
    cudaGetSymbolAddress((void**)&attl, g_attl);
    cudaGetSymbolAddress((void**)&wh, g_wh);
    cudaGetSymbolAddress((void**)&wl, g_wl);

    cudaFuncSetAttribute(gemm_bf16x3_kernel,
                         cudaFuncAttributeMaxDynamicSharedMemorySize, GEMM_SMEM);
    cudaFuncSetAttribute(ctx_mma_kernel,
                         cudaFuncAttributeMaxDynamicSharedMemorySize, CTX_SMEM);
    cudaFuncSetAttribute(attn_mma_kernel,
                         cudaFuncAttributeMaxDynamicSharedMemorySize, AT_SMEM);

    const int WN = DIMQ * DIMQ;

    hilo_kernel<<<(NT * DIMQ) / (256 * 4), 256>>>(x, xh, xl);
    WPtrs wp; wp.w[0] = Wq; wp.w[1] = Wk; wp.w[2] = Wv; wp.w[3] = Wp;
    hilo_w4_kernel<<<dim3(WN / (256 * 4), 4), 256>>>(wp, wh, wl);

    // merged QKV GEMM: all outputs bf16 hi/lo; softmax on q,k
    OutPtrs opqkv;
    opqkv.h[0] = qh; opqkv.h[1] = kh; opqkv.h[2] = vh;
    opqkv.l[0] = ql; opqkv.l[1] = kl; opqkv.l[2] = vl;
    gemm_bf16x3_kernel<<<dim3(3 * DIMQ / GBN, NT / GBM), 512, GEMM_SMEM>>>(
        xh, xl, wh, wl, bq, bk, bv, nullptr, opqkv, 0b011);

    ctx_mma_kernel<<<dim3(NB * HEADS, NSPLIT), 128, CTX_SMEM>>>(
        kh, kl, vh, vl, ctxp, ksump);
    ctx_reduce_kernel<<<NB * HEADS, 256>>>(ctxp, ksump, cth, ctl, ksum);

    attn_mma_kernel<<<dim3(NB * HEADS, TLEN / 128), 128, AT_SMEM>>>(
        qh, ql, cth, ctl, ksum, atth, attl);

    // output projection -> fp32 out
    OutPtrs opf = {};
    gemm_bf16x3_kernel<<<dim3(DIMQ / GBN, NT / GBM), 512, GEMM_SMEM>>>(
        atth, attl, wh + 3 * WN, wl + 3 * WN, bp, bp, bp, out, opf, 0);
}